// round 12
// baseline (speedup 1.0000x reference)
#include <cuda_runtime.h>
#include <cuda_bf16.h>
#include <cstdint>

// ---------------- problem constants ----------------
#define NWIN   2048
#define NTOK   66
#define MTOT   (NWIN * NTOK)       // 135168
#define DIM    256
#define QKVN   768
#define NHEAD  8
#define HD     32
#define TOKNUM 2
#define GK     256

// ---------------- scratch ----------------
__device__ float          g_qkv [(size_t)MTOT * QKVN];
__device__ __nv_bfloat16  g_xhi [(size_t)MTOT * DIM];
__device__ __nv_bfloat16  g_xlo [(size_t)MTOT * DIM];
__device__ __nv_bfloat16  g_ahi [(size_t)MTOT * DIM];
__device__ __nv_bfloat16  g_alo [(size_t)MTOT * DIM];
__device__ __nv_bfloat16  g_qwhi[(size_t)QKVN * DIM];
__device__ __nv_bfloat16  g_qwlo[(size_t)QKVN * DIM];
__device__ __nv_bfloat16  g_pwhi[(size_t)DIM * DIM];
__device__ __nv_bfloat16  g_pwlo[(size_t)DIM * DIM];

// ---------------- helpers ----------------
__device__ __forceinline__ uint32_t smem_u32(const void* p) {
    uint32_t a;
    asm("{ .reg .u64 t; cvta.to.shared.u64 t, %1; cvt.u32.u64 %0, t; }"
        : "=r"(a) : "l"(p));
    return a;
}
__device__ __forceinline__ void ldsm4(uint32_t* r, uint32_t addr) {
    asm volatile("ldmatrix.sync.aligned.m8n8.x4.shared.b16 {%0,%1,%2,%3}, [%4];"
                 : "=r"(r[0]), "=r"(r[1]), "=r"(r[2]), "=r"(r[3]) : "r"(addr));
}
__device__ __forceinline__ void ldsm4t(uint32_t* r, uint32_t addr) {
    asm volatile("ldmatrix.sync.aligned.m8n8.x4.trans.shared.b16 {%0,%1,%2,%3}, [%4];"
                 : "=r"(r[0]), "=r"(r[1]), "=r"(r[2]), "=r"(r[3]) : "r"(addr));
}
__device__ __forceinline__ void mma_bf16(float* c, const uint32_t* a,
                                         uint32_t b0, uint32_t b1) {
    asm volatile("mma.sync.aligned.m16n8k16.row.col.f32.bf16.bf16.f32 "
                 "{%0,%1,%2,%3}, {%4,%5,%6,%7}, {%8,%9}, {%0,%1,%2,%3};"
                 : "+f"(c[0]), "+f"(c[1]), "+f"(c[2]), "+f"(c[3])
                 : "r"(a[0]), "r"(a[1]), "r"(a[2]), "r"(a[3]),
                   "r"(b0), "r"(b1));
}
#define CP_ASYNC16(dst, src) \
    asm volatile("cp.async.cg.shared.global [%0], [%1], 16;" :: "r"(dst), "l"(src))
#define CP_COMMIT() asm volatile("cp.async.commit_group;" ::: "memory")

// ---------------- fp32 -> bf16 hi/lo split ----------------
__global__ void split_kernel(const float* __restrict__ in,
                             __nv_bfloat16* __restrict__ hi,
                             __nv_bfloat16* __restrict__ lo, int n4)
{
    int i = blockIdx.x * blockDim.x + threadIdx.x;
    if (i >= n4) return;
    float4 v = ((const float4*)in)[i];
    __nv_bfloat16 h0 = __float2bfloat16(v.x);
    __nv_bfloat16 h1 = __float2bfloat16(v.y);
    __nv_bfloat16 h2 = __float2bfloat16(v.z);
    __nv_bfloat16 h3 = __float2bfloat16(v.w);
    __nv_bfloat16 l0 = __float2bfloat16(v.x - __bfloat162float(h0));
    __nv_bfloat16 l1 = __float2bfloat16(v.y - __bfloat162float(h1));
    __nv_bfloat16 l2 = __float2bfloat16(v.z - __bfloat162float(h2));
    __nv_bfloat16 l3 = __float2bfloat16(v.w - __bfloat162float(h3));
    ((__nv_bfloat162*)hi)[2 * i + 0] = __nv_bfloat162(h0, h1);
    ((__nv_bfloat162*)hi)[2 * i + 1] = __nv_bfloat162(h2, h3);
    ((__nv_bfloat162*)lo)[2 * i + 0] = __nv_bfloat162(l0, l1);
    ((__nv_bfloat162*)lo)[2 * i + 1] = __nv_bfloat162(l2, l3);
}

// ---------------- HMMA GEMM: BK=32, swizzled 3-stage, 1 sync/chunk ---------
#define BM 128
#define BN 128
#define BKK 32
#define ROWB 64u
#define ARR_BYTES (128u * ROWB)
#define STAGE_BYTES (4u * ARR_BYTES)
#define STAGES 3
#define GEMM_SMEM (STAGES * STAGE_BYTES)  // 98304
#define NCHUNK (GK / BKK)                 // 8

__device__ __forceinline__ uint32_t swz(uint32_t row, uint32_t ch) {
    return row * ROWB + ((ch ^ ((row >> 1) & 3u)) << 4);
}

__global__ __launch_bounds__(256, 2)
void gemm_mma_kernel(const __nv_bfloat16* __restrict__ Ahi,
                     const __nv_bfloat16* __restrict__ Alo,
                     const __nv_bfloat16* __restrict__ Bhi,
                     const __nv_bfloat16* __restrict__ Blo,
                     const float* __restrict__ bias,
                     float* __restrict__ C, int N)
{
    extern __shared__ __nv_bfloat16 smbuf[];
    const uint32_t sbase = smem_u32(smbuf);
    const int tid  = threadIdx.x;
    const int lane = tid & 31;
    const int wid  = tid >> 5;
    const int wm   = wid >> 2;
    const int wn   = wid & 3;
    const int m0 = blockIdx.x * BM;
    const int n0 = blockIdx.y * BN;

    float acc[4][4][4];
#pragma unroll
    for (int i = 0; i < 4; i++)
#pragma unroll
        for (int j = 0; j < 4; j++)
#pragma unroll
            for (int q = 0; q < 4; q++) acc[i][j][q] = 0.0f;

    auto load_stage = [&](int c, int s) {
        const int k0 = c * BKK;
        const uint32_t stb = sbase + (uint32_t)s * STAGE_BYTES;
#pragma unroll
        for (int it = 0; it < 8; it++) {
            int t = tid + it * 256;
            int arr = t >> 9;
            int rem = t & 511;
            uint32_t row = (uint32_t)(rem >> 2);
            uint32_t ch  = (uint32_t)(rem & 3);
            const __nv_bfloat16* g;
            if (arr == 0)      g = Ahi + (size_t)(m0 + row) * GK + k0 + ch * 8;
            else if (arr == 1) g = Alo + (size_t)(m0 + row) * GK + k0 + ch * 8;
            else if (arr == 2) g = Bhi + (size_t)(n0 + row) * GK + k0 + ch * 8;
            else               g = Blo + (size_t)(n0 + row) * GK + k0 + ch * 8;
            uint32_t dst = stb + (uint32_t)arr * ARR_BYTES + swz(row, ch);
            CP_ASYNC16(dst, g);
        }
        CP_COMMIT();
    };

    load_stage(0, 0);
    load_stage(1, 1);

    const int a_row = (lane & 15);
    const int b_row = (lane & 7) + ((lane >> 4) << 3);

    int stage = 0;
    for (int c = 0; c < NCHUNK; c++) {
        if (c < NCHUNK - 1) asm volatile("cp.async.wait_group 1;" ::: "memory");
        else                asm volatile("cp.async.wait_group 0;" ::: "memory");
        __syncthreads();
        if (c + 2 < NCHUNK) {
            int s2 = stage + 2; if (s2 >= STAGES) s2 -= STAGES;
            load_stage(c + 2, s2);
        }

        const uint32_t st = sbase + (uint32_t)stage * STAGE_BYTES;
        const uint32_t sAhi = st;
        const uint32_t sAlo = st + ARR_BYTES;
        const uint32_t sBhi = st + 2u * ARR_BYTES;
        const uint32_t sBlo = st + 3u * ARR_BYTES;

#pragma unroll
        for (int ks = 0; ks < 2; ks++) {
            uint32_t ah[4][4], al[4][4], bh[2][4], bl[2][4];
#pragma unroll
            for (int mi = 0; mi < 4; mi++) {
                uint32_t row = (uint32_t)(wm * 64 + mi * 16 + a_row);
                uint32_t ch  = (uint32_t)(ks * 2 + (lane >> 4));
                uint32_t off = swz(row, ch);
                ldsm4(ah[mi], sAhi + off);
                ldsm4(al[mi], sAlo + off);
            }
#pragma unroll
            for (int nt = 0; nt < 2; nt++) {
                uint32_t row = (uint32_t)(wn * 32 + nt * 16 + b_row);
                uint32_t ch  = (uint32_t)(ks * 2 + ((lane >> 3) & 1));
                uint32_t off = swz(row, ch);
                ldsm4(bh[nt], sBhi + off);
                ldsm4(bl[nt], sBlo + off);
            }
#pragma unroll
            for (int mi = 0; mi < 4; mi++)
#pragma unroll
                for (int nj = 0; nj < 4; nj++)
                    mma_bf16(acc[mi][nj], ah[mi],
                             bh[nj >> 1][(nj & 1) * 2], bh[nj >> 1][(nj & 1) * 2 + 1]);
#pragma unroll
            for (int mi = 0; mi < 4; mi++)
#pragma unroll
                for (int nj = 0; nj < 4; nj++)
                    mma_bf16(acc[mi][nj], ah[mi],
                             bl[nj >> 1][(nj & 1) * 2], bl[nj >> 1][(nj & 1) * 2 + 1]);
#pragma unroll
            for (int mi = 0; mi < 4; mi++)
#pragma unroll
                for (int nj = 0; nj < 4; nj++)
                    mma_bf16(acc[mi][nj], al[mi],
                             bh[nj >> 1][(nj & 1) * 2], bh[nj >> 1][(nj & 1) * 2 + 1]);
        }
        if (++stage >= STAGES) stage = 0;
    }

#pragma unroll
    for (int mi = 0; mi < 4; mi++) {
        int row = m0 + wm * 64 + mi * 16 + (lane >> 2);
#pragma unroll
        for (int nj = 0; nj < 4; nj++) {
            int col = n0 + wn * 32 + nj * 8 + (lane & 3) * 2;
            float2 bv = *(const float2*)&bias[col];
            float2 v0 = make_float2(acc[mi][nj][0] + bv.x, acc[mi][nj][1] + bv.y);
            float2 v1 = make_float2(acc[mi][nj][2] + bv.x, acc[mi][nj][3] + bv.y);
            *(float2*)&C[(size_t)row * N + col] = v0;
            *(float2*)&C[(size_t)(row + 8) * N + col] = v1;
        }
    }
}

// ---------------- MMA attention: one CTA per window, 8 heads sequential ----
// Padded sizes: rows 66 -> 80 for Q/K/V and S/P tiles.
// smem byte layout:
#define SQ_HI 0
#define SK_HI 10240
#define SV_HI 20480
#define MAT_LO 5120                 // lo array offset within each 10240 pair
#define SS    30720                 // fp32 [80][81]
#define SP_HI 56640                 // bf16 [80][88]
#define SP_LO 70720                 // bf16 [80][88]
#define STAB  84800                 // 1800 floats
#define ATTN_SMEM 92000

__global__ __launch_bounds__(256, 2)
void attn_mma_kernel(const float* __restrict__ qkv,
                     const float* __restrict__ table,
                     __nv_bfloat16* __restrict__ ohi,
                     __nv_bfloat16* __restrict__ olo)
{
    extern __shared__ char smc[];
    const uint32_t sb = smem_u32(smc);
    float* Ssm = (float*)(smc + SS);
    float* tab = (float*)(smc + STAB);

    const int b = blockIdx.x;
    const int tid = threadIdx.x;
    const int lane = tid & 31;
    const int wid = tid >> 5;
    const size_t base = (size_t)b * NTOK * QKVN;
    const float scale = 0.1767766952966369f;

    // one-time init: bias table + zero both P arrays (pad cols/rows stay 0)
    for (int t = tid; t < 1800; t += 256) tab[t] = table[t];
    for (int t = tid; t < (2 * 80 * 88 * 2) / 16; t += 256)
        ((uint4*)(smc + SP_HI))[t] = make_uint4(0, 0, 0, 0);

    const int a_row = (lane & 15);
    const int b_row = (lane & 7) + ((lane >> 4) << 3);

    for (int h = 0; h < NHEAD; h++) {
        __syncthreads();   // protects Q/K/V (+P) reuse from previous head

        // ---- convert: Q/K/V head h -> bf16 hi/lo swizzled smem ----
        for (int it = tid; it < 960; it += 256) {
            int mat = it / 320;            // 0 Q, 1 K, 2 V
            int rem = it - mat * 320;
            int row = rem >> 2;
            int ch  = rem & 3;
            uint32_t dhi = (uint32_t)(mat * 10240) + swz((uint32_t)row, (uint32_t)ch);
            uint32_t r0, r1, r2, r3, s0, s1, s2, s3;
            if (row < NTOK) {
                const float* src = qkv + base + (size_t)row * QKVN + mat * 256 + h * HD + ch * 8;
                float4 f0 = *(const float4*)src;
                float4 f1 = *(const float4*)(src + 4);
                if (mat == 0) {
                    f0.x *= scale; f0.y *= scale; f0.z *= scale; f0.w *= scale;
                    f1.x *= scale; f1.y *= scale; f1.z *= scale; f1.w *= scale;
                }
                float v[8] = {f0.x, f0.y, f0.z, f0.w, f1.x, f1.y, f1.z, f1.w};
                __nv_bfloat16 hh[8], ll[8];
#pragma unroll
                for (int e = 0; e < 8; e++) {
                    hh[e] = __float2bfloat16(v[e]);
                    ll[e] = __float2bfloat16(v[e] - __bfloat162float(hh[e]));
                }
                uint32_t* ph = (uint32_t*)hh;
                uint32_t* pl = (uint32_t*)ll;
                r0 = ph[0]; r1 = ph[1]; r2 = ph[2]; r3 = ph[3];
                s0 = pl[0]; s1 = pl[1]; s2 = pl[2]; s3 = pl[3];
            } else {
                r0 = r1 = r2 = r3 = 0u;
                s0 = s1 = s2 = s3 = 0u;
            }
            *(uint4*)(smc + dhi) = make_uint4(r0, r1, r2, r3);
            *(uint4*)(smc + dhi + MAT_LO) = make_uint4(s0, s1, s2, s3);
        }
        __syncthreads();

        // ---- S = Q K^T : 25 units (5 m16-tiles x 5 n16-groups) ----
        for (int u = wid; u < 25; u += 8) {
            int mt = u / 5, ng = u - (u / 5) * 5;
            float acc[2][4] = {{0.f, 0.f, 0.f, 0.f}, {0.f, 0.f, 0.f, 0.f}};
#pragma unroll
            for (int ks = 0; ks < 2; ks++) {
                uint32_t ah[4], al[4], bh[4], bl[4];
                uint32_t aoff = swz((uint32_t)(mt * 16 + a_row),
                                    (uint32_t)(ks * 2 + (lane >> 4)));
                ldsm4(ah, sb + SQ_HI + aoff);
                ldsm4(al, sb + SQ_HI + MAT_LO + aoff);
                uint32_t boff = swz((uint32_t)(ng * 16 + b_row),
                                    (uint32_t)(ks * 2 + ((lane >> 3) & 1)));
                ldsm4(bh, sb + SK_HI + boff);
                ldsm4(bl, sb + SK_HI + MAT_LO + boff);
#pragma unroll
                for (int nj = 0; nj < 2; nj++) {
                    mma_bf16(acc[nj], ah, bh[nj * 2], bh[nj * 2 + 1]);
                    mma_bf16(acc[nj], ah, bl[nj * 2], bl[nj * 2 + 1]);
                    mma_bf16(acc[nj], al, bh[nj * 2], bh[nj * 2 + 1]);
                }
            }
            int r = mt * 16 + (lane >> 2);
#pragma unroll
            for (int nj = 0; nj < 2; nj++) {
                int c = ng * 16 + nj * 8 + (lane & 3) * 2;
                Ssm[r * 81 + c]       = acc[nj][0];
                Ssm[r * 81 + c + 1]   = acc[nj][1];
                Ssm[(r + 8) * 81 + c]     = acc[nj][2];
                Ssm[(r + 8) * 81 + c + 1] = acc[nj][3];
            }
        }
        __syncthreads();

        // ---- softmax rows (+bias): 160 threads, 2 per row ----
        if (tid < 160) {
            int i  = tid >> 1;
            int hf = tid & 1;
            int c0 = hf * 33;
            const bool ab = (i >= TOKNUM && i < NTOK);
            int si = ab ? (i - TOKNUM) : 0;
            int yi = si >> 3, xi = si & 7;
            float* Srow = Ssm + i * 81;
            float mx = -1e30f;
            for (int j = c0; j < c0 + 33; j++) {
                float v = Srow[j];
                if (ab && j >= TOKNUM) {
                    int sj = j - TOKNUM;
                    int rel = (yi - (sj >> 3) + 7) * 15 + (xi - (sj & 7) + 7);
                    v += tab[rel * NHEAD + h];
                    Srow[j] = v;
                }
                mx = fmaxf(mx, v);
            }
            mx = fmaxf(mx, __shfl_xor_sync(0xFFFFFFFFu, mx, 1));
            float sum = 0.f;
            for (int j = c0; j < c0 + 33; j++) {
                float p = __expf(Srow[j] - mx);
                Srow[j] = p;
                sum += p;
            }
            sum += __shfl_xor_sync(0xFFFFFFFFu, sum, 1);
            float inv = 1.0f / sum;
            __nv_bfloat16* ph = (__nv_bfloat16*)(smc + SP_HI) + i * 88;
            __nv_bfloat16* pl = (__nv_bfloat16*)(smc + SP_LO) + i * 88;
            for (int j = c0; j < c0 + 33; j++) {
                float p = Srow[j] * inv;
                __nv_bfloat16 hh = __float2bfloat16(p);
                ph[j] = hh;
                pl[j] = __float2bfloat16(p - __bfloat162float(hh));
            }
        }
        __syncthreads();

        // ---- O = P V : 10 units (5 m16-tiles x 2 n16-groups), K=80 ----
        for (int u = wid; u < 10; u += 8) {
            int mt = u >> 1, ng = u & 1;
            float acc[2][4] = {{0.f, 0.f, 0.f, 0.f}, {0.f, 0.f, 0.f, 0.f}};
#pragma unroll
            for (int ks = 0; ks < 5; ks++) {
                uint32_t ah[4], al[4], bh[4], bl[4];
                uint32_t aoff = (uint32_t)((mt * 16 + a_row) * 176 +
                                           (ks * 2 + (lane >> 4)) * 16);
                ldsm4(ah, sb + SP_HI + aoff);
                ldsm4(al, sb + SP_LO + aoff);
                uint32_t vrow = (uint32_t)(ks * 16 + (lane & 7) + (((lane >> 3) & 1) << 3));
                uint32_t vch  = (uint32_t)(ng * 2 + (lane >> 4));
                uint32_t boff = swz(vrow, vch);
                ldsm4t(bh, sb + SV_HI + boff);
                ldsm4t(bl, sb + SV_HI + MAT_LO + boff);
#pragma unroll
                for (int nj = 0; nj < 2; nj++) {
                    mma_bf16(acc[nj], ah, bh[nj * 2], bh[nj * 2 + 1]);
                    mma_bf16(acc[nj], ah, bl[nj * 2], bl[nj * 2 + 1]);
                    mma_bf16(acc[nj], al, bh[nj * 2], bh[nj * 2 + 1]);
                }
            }
            int r0 = mt * 16 + (lane >> 2);
#pragma unroll
            for (int nj = 0; nj < 2; nj++) {
                int c = ng * 16 + nj * 8 + (lane & 3) * 2;
#pragma unroll
                for (int half = 0; half < 2; half++) {
                    int tok = r0 + half * 8;
                    if (tok < NTOK) {
                        float o0 = acc[nj][half * 2];
                        float o1 = acc[nj][half * 2 + 1];
                        __nv_bfloat16 h0 = __float2bfloat16(o0);
                        __nv_bfloat16 h1 = __float2bfloat16(o1);
                        __nv_bfloat16 l0 = __float2bfloat16(o0 - __bfloat162float(h0));
                        __nv_bfloat16 l1 = __float2bfloat16(o1 - __bfloat162float(h1));
                        size_t go = ((size_t)b * NTOK + tok) * DIM + h * HD + c;
                        *(__nv_bfloat162*)(ohi + go) = __nv_bfloat162(h0, h1);
                        *(__nv_bfloat162*)(olo + go) = __nv_bfloat162(l0, l1);
                    }
                }
            }
        }
    }
}

// ---------------------------------------------------------------------------
extern "C" void kernel_launch(void* const* d_in, const int* in_sizes, int n_in,
                              void* d_out, int out_size)
{
    const float* x      = (const float*)d_in[0];
    const float* qkv_w  = (const float*)d_in[1];
    const float* qkv_b  = (const float*)d_in[2];
    const float* table  = (const float*)d_in[3];
    const float* proj_w = (const float*)d_in[4];
    const float* proj_b = (const float*)d_in[5];
    float* out = (float*)d_out;

    __nv_bfloat16 *xhi, *xlo, *ahi, *alo, *qwhi, *qwlo, *pwhi, *pwlo;
    float* qkv_s;
    cudaGetSymbolAddress((void**)&qkv_s, g_qkv);
    cudaGetSymbolAddress((void**)&xhi,  g_xhi);
    cudaGetSymbolAddress((void**)&xlo,  g_xlo);
    cudaGetSymbolAddress((void**)&ahi,  g_ahi);
    cudaGetSymbolAddress((void**)&alo,  g_alo);
    cudaGetSymbolAddress((void**)&qwhi, g_qwhi);
    cudaGetSymbolAddress((void**)&qwlo, g_qwlo);
    cudaGetSymbolAddress((void**)&pwhi, g_pwhi);
    cudaGetSymbolAddress((void**)&pwlo, g_pwlo);

    cudaFuncSetAttribute(gemm_mma_kernel, cudaFuncAttributeMaxDynamicSharedMemorySize, GEMM_SMEM);
    cudaFuncSetAttribute(attn_mma_kernel, cudaFuncAttributeMaxDynamicSharedMemorySize, ATTN_SMEM);

    {
        int n4 = MTOT * DIM / 4;
        split_kernel<<<(n4 + 255) / 256, 256>>>(x, xhi, xlo, n4);
        int w4 = QKVN * DIM / 4;
        split_kernel<<<(w4 + 255) / 256, 256>>>(qkv_w, qwhi, qwlo, w4);
        int p4 = DIM * DIM / 4;
        split_kernel<<<(p4 + 255) / 256, 256>>>(proj_w, pwhi, pwlo, p4);
    }

    gemm_mma_kernel<<<dim3(MTOT / BM, QKVN / BN), 256, GEMM_SMEM>>>(
        xhi, xlo, qwhi, qwlo, qkv_b, qkv_s, QKVN);

    attn_mma_kernel<<<NWIN, 256, ATTN_SMEM>>>(qkv_s, table, ahi, alo);

    gemm_mma_kernel<<<dim3(MTOT / BM, DIM / BN), 256, GEMM_SMEM>>>(
        ahi, alo, pwhi, pwlo, proj_b, out, DIM);
}

// round 16
// speedup vs baseline: 1.4023x; 1.4023x over previous
#include <cuda_runtime.h>
#include <cuda_bf16.h>
#include <cstdint>

// ---------------- problem constants ----------------
#define NWIN   2048
#define NTOK   66
#define MTOT   (NWIN * NTOK)       // 135168
#define DIM    256
#define QKVN   768
#define NHEAD  8
#define HD     32
#define TOKNUM 2
#define GK     256

// ---------------- scratch ----------------
__device__ __nv_bfloat16  g_qkvhi[(size_t)MTOT * QKVN];
__device__ __nv_bfloat16  g_qkvlo[(size_t)MTOT * QKVN];
__device__ __nv_bfloat16  g_xhi [(size_t)MTOT * DIM];
__device__ __nv_bfloat16  g_xlo [(size_t)MTOT * DIM];
__device__ __nv_bfloat16  g_ahi [(size_t)MTOT * DIM];
__device__ __nv_bfloat16  g_alo [(size_t)MTOT * DIM];
__device__ __nv_bfloat16  g_qwhi[(size_t)QKVN * DIM];
__device__ __nv_bfloat16  g_qwlo[(size_t)QKVN * DIM];
__device__ __nv_bfloat16  g_pwhi[(size_t)DIM * DIM];
__device__ __nv_bfloat16  g_pwlo[(size_t)DIM * DIM];

// ---------------- helpers ----------------
__device__ __forceinline__ uint32_t smem_u32(const void* p) {
    uint32_t a;
    asm("{ .reg .u64 t; cvta.to.shared.u64 t, %1; cvt.u32.u64 %0, t; }"
        : "=r"(a) : "l"(p));
    return a;
}
__device__ __forceinline__ void ldsm4(uint32_t* r, uint32_t addr) {
    asm volatile("ldmatrix.sync.aligned.m8n8.x4.shared.b16 {%0,%1,%2,%3}, [%4];"
                 : "=r"(r[0]), "=r"(r[1]), "=r"(r[2]), "=r"(r[3]) : "r"(addr));
}
__device__ __forceinline__ void ldsm4t(uint32_t* r, uint32_t addr) {
    asm volatile("ldmatrix.sync.aligned.m8n8.x4.trans.shared.b16 {%0,%1,%2,%3}, [%4];"
                 : "=r"(r[0]), "=r"(r[1]), "=r"(r[2]), "=r"(r[3]) : "r"(addr));
}
__device__ __forceinline__ void mma_bf16(float* c, const uint32_t* a,
                                         uint32_t b0, uint32_t b1) {
    asm volatile("mma.sync.aligned.m16n8k16.row.col.f32.bf16.bf16.f32 "
                 "{%0,%1,%2,%3}, {%4,%5,%6,%7}, {%8,%9}, {%0,%1,%2,%3};"
                 : "+f"(c[0]), "+f"(c[1]), "+f"(c[2]), "+f"(c[3])
                 : "r"(a[0]), "r"(a[1]), "r"(a[2]), "r"(a[3]),
                   "r"(b0), "r"(b1));
}
__device__ __forceinline__ uint32_t pack_bf2(float x, float y) {
    __nv_bfloat162 t(__float2bfloat16(x), __float2bfloat16(y));
    return *(uint32_t*)&t;
}
__device__ __forceinline__ float bf_lo(float x) {
    return x - __bfloat162float(__float2bfloat16(x));
}
#define CP_ASYNC16(dst, src) \
    asm volatile("cp.async.cg.shared.global [%0], [%1], 16;" :: "r"(dst), "l"(src))
#define CP_COMMIT() asm volatile("cp.async.commit_group;" ::: "memory")

// ---------------- fp32 -> bf16 hi/lo split ----------------
__global__ void split_kernel(const float* __restrict__ in,
                             __nv_bfloat16* __restrict__ hi,
                             __nv_bfloat16* __restrict__ lo, int n4)
{
    int i = blockIdx.x * blockDim.x + threadIdx.x;
    if (i >= n4) return;
    float4 v = ((const float4*)in)[i];
    __nv_bfloat16 h0 = __float2bfloat16(v.x);
    __nv_bfloat16 h1 = __float2bfloat16(v.y);
    __nv_bfloat16 h2 = __float2bfloat16(v.z);
    __nv_bfloat16 h3 = __float2bfloat16(v.w);
    __nv_bfloat16 l0 = __float2bfloat16(v.x - __bfloat162float(h0));
    __nv_bfloat16 l1 = __float2bfloat16(v.y - __bfloat162float(h1));
    __nv_bfloat16 l2 = __float2bfloat16(v.z - __bfloat162float(h2));
    __nv_bfloat16 l3 = __float2bfloat16(v.w - __bfloat162float(h3));
    ((__nv_bfloat162*)hi)[2 * i + 0] = __nv_bfloat162(h0, h1);
    ((__nv_bfloat162*)hi)[2 * i + 1] = __nv_bfloat162(h2, h3);
    ((__nv_bfloat162*)lo)[2 * i + 0] = __nv_bfloat162(l0, l1);
    ((__nv_bfloat162*)lo)[2 * i + 1] = __nv_bfloat162(l2, l3);
}

// ---------------- HMMA GEMM: BK=32, swizzled 3-stage, 1 sync/chunk ---------
// Epilogue: fp32 (Cf) or bf16 hi/lo (Chi/Clo).
#define BM 128
#define BN 128
#define BKK 32
#define ROWB 64u
#define ARR_BYTES (128u * ROWB)
#define STAGE_BYTES (4u * ARR_BYTES)
#define STAGES 3
#define GEMM_SMEM (STAGES * STAGE_BYTES)  // 98304
#define NCHUNK (GK / BKK)                 // 8

__device__ __forceinline__ uint32_t swz(uint32_t row, uint32_t ch) {
    return row * ROWB + ((ch ^ ((row >> 1) & 3u)) << 4);
}

__global__ __launch_bounds__(256, 2)
void gemm_mma_kernel(const __nv_bfloat16* __restrict__ Ahi,
                     const __nv_bfloat16* __restrict__ Alo,
                     const __nv_bfloat16* __restrict__ Bhi,
                     const __nv_bfloat16* __restrict__ Blo,
                     const float* __restrict__ bias,
                     float* __restrict__ Cf,
                     __nv_bfloat16* __restrict__ Chi,
                     __nv_bfloat16* __restrict__ Clo, int N)
{
    extern __shared__ __nv_bfloat16 smbuf[];
    const uint32_t sbase = smem_u32(smbuf);
    const int tid  = threadIdx.x;
    const int lane = tid & 31;
    const int wid  = tid >> 5;
    const int wm   = wid >> 2;
    const int wn   = wid & 3;
    const int m0 = blockIdx.x * BM;
    const int n0 = blockIdx.y * BN;

    float acc[4][4][4];
#pragma unroll
    for (int i = 0; i < 4; i++)
#pragma unroll
        for (int j = 0; j < 4; j++)
#pragma unroll
            for (int q = 0; q < 4; q++) acc[i][j][q] = 0.0f;

    auto load_stage = [&](int c, int s) {
        const int k0 = c * BKK;
        const uint32_t stb = sbase + (uint32_t)s * STAGE_BYTES;
#pragma unroll
        for (int it = 0; it < 8; it++) {
            int t = tid + it * 256;
            int arr = t >> 9;
            int rem = t & 511;
            uint32_t row = (uint32_t)(rem >> 2);
            uint32_t ch  = (uint32_t)(rem & 3);
            const __nv_bfloat16* g;
            if (arr == 0)      g = Ahi + (size_t)(m0 + row) * GK + k0 + ch * 8;
            else if (arr == 1) g = Alo + (size_t)(m0 + row) * GK + k0 + ch * 8;
            else if (arr == 2) g = Bhi + (size_t)(n0 + row) * GK + k0 + ch * 8;
            else               g = Blo + (size_t)(n0 + row) * GK + k0 + ch * 8;
            uint32_t dst = stb + (uint32_t)arr * ARR_BYTES + swz(row, ch);
            CP_ASYNC16(dst, g);
        }
        CP_COMMIT();
    };

    load_stage(0, 0);
    load_stage(1, 1);

    const int a_row = (lane & 15);
    const int b_row = (lane & 7) + ((lane >> 4) << 3);

    int stage = 0;
    for (int c = 0; c < NCHUNK; c++) {
        if (c < NCHUNK - 1) asm volatile("cp.async.wait_group 1;" ::: "memory");
        else                asm volatile("cp.async.wait_group 0;" ::: "memory");
        __syncthreads();
        if (c + 2 < NCHUNK) {
            int s2 = stage + 2; if (s2 >= STAGES) s2 -= STAGES;
            load_stage(c + 2, s2);
        }

        const uint32_t st = sbase + (uint32_t)stage * STAGE_BYTES;
        const uint32_t sAhi = st;
        const uint32_t sAlo = st + ARR_BYTES;
        const uint32_t sBhi = st + 2u * ARR_BYTES;
        const uint32_t sBlo = st + 3u * ARR_BYTES;

#pragma unroll
        for (int ks = 0; ks < 2; ks++) {
            uint32_t ah[4][4], al[4][4], bh[2][4], bl[2][4];
#pragma unroll
            for (int mi = 0; mi < 4; mi++) {
                uint32_t row = (uint32_t)(wm * 64 + mi * 16 + a_row);
                uint32_t ch  = (uint32_t)(ks * 2 + (lane >> 4));
                uint32_t off = swz(row, ch);
                ldsm4(ah[mi], sAhi + off);
                ldsm4(al[mi], sAlo + off);
            }
#pragma unroll
            for (int nt = 0; nt < 2; nt++) {
                uint32_t row = (uint32_t)(wn * 32 + nt * 16 + b_row);
                uint32_t ch  = (uint32_t)(ks * 2 + ((lane >> 3) & 1));
                uint32_t off = swz(row, ch);
                ldsm4(bh[nt], sBhi + off);
                ldsm4(bl[nt], sBlo + off);
            }
#pragma unroll
            for (int mi = 0; mi < 4; mi++)
#pragma unroll
                for (int nj = 0; nj < 4; nj++)
                    mma_bf16(acc[mi][nj], ah[mi],
                             bh[nj >> 1][(nj & 1) * 2], bh[nj >> 1][(nj & 1) * 2 + 1]);
#pragma unroll
            for (int mi = 0; mi < 4; mi++)
#pragma unroll
                for (int nj = 0; nj < 4; nj++)
                    mma_bf16(acc[mi][nj], ah[mi],
                             bl[nj >> 1][(nj & 1) * 2], bl[nj >> 1][(nj & 1) * 2 + 1]);
#pragma unroll
            for (int mi = 0; mi < 4; mi++)
#pragma unroll
                for (int nj = 0; nj < 4; nj++)
                    mma_bf16(acc[mi][nj], al[mi],
                             bh[nj >> 1][(nj & 1) * 2], bh[nj >> 1][(nj & 1) * 2 + 1]);
        }
        if (++stage >= STAGES) stage = 0;
    }

#pragma unroll
    for (int mi = 0; mi < 4; mi++) {
        int row = m0 + wm * 64 + mi * 16 + (lane >> 2);
#pragma unroll
        for (int nj = 0; nj < 4; nj++) {
            int col = n0 + wn * 32 + nj * 8 + (lane & 3) * 2;
            float2 bv = *(const float2*)&bias[col];
            float v0 = acc[mi][nj][0] + bv.x, v1 = acc[mi][nj][1] + bv.y;
            float v2 = acc[mi][nj][2] + bv.x, v3 = acc[mi][nj][3] + bv.y;
            if (Cf) {
                *(float2*)&Cf[(size_t)row * N + col] = make_float2(v0, v1);
                *(float2*)&Cf[(size_t)(row + 8) * N + col] = make_float2(v2, v3);
            } else {
                size_t o0 = (size_t)row * N + col;
                size_t o1 = (size_t)(row + 8) * N + col;
                uint32_t h01 = pack_bf2(v0, v1), h23 = pack_bf2(v2, v3);
                uint32_t l01 = pack_bf2(bf_lo(v0), bf_lo(v1));
                uint32_t l23 = pack_bf2(bf_lo(v2), bf_lo(v3));
                *(uint32_t*)&Chi[o0] = h01;  *(uint32_t*)&Chi[o1] = h23;
                *(uint32_t*)&Clo[o0] = l01;  *(uint32_t*)&Clo[o1] = l23;
            }
        }
    }
}

// ---------------- flash MMA attention: CTA=(window, 2 heads), 5 warps ------
// smem: 12 arrays [80 rows x 64B swizzled]: (lh,mat{Q,K,V}) x (hi,lo), + table.
#define AT_ARR 5120
#define AT_TAB (12 * AT_ARR)          // 61440
#define ATT_SMEM (AT_TAB + 7200)      // 68640

__global__ __launch_bounds__(160, 2)
void attn_flash_kernel(const __nv_bfloat16* __restrict__ qh_g,
                       const __nv_bfloat16* __restrict__ ql_g,
                       const float* __restrict__ table,
                       __nv_bfloat16* __restrict__ ohi,
                       __nv_bfloat16* __restrict__ olo)
{
    extern __shared__ char smc[];
    const uint32_t sb = smem_u32(smc);
    float* tab = (float*)(smc + AT_TAB);

    const int b = blockIdx.x;
    const int h0 = blockIdx.y * 2;
    const int tid = threadIdx.x;
    const int lane = tid & 31;
    const int wid = tid >> 5;            // 0..4 = stripe
    const float scale = 0.1767766952966369f;

    // ---- stage Q/K/V (2 heads, hi+lo) via cp.async; zero pad rows ----
    for (int u = tid; u < 1584; u += 160) {
        int arr6 = u / 264;              // lh*3 + mat
        int rem = u - arr6 * 264;
        int row = rem >> 2, ch = rem & 3;
        int lh = arr6 / 3, m = arr6 - lh * 3;
        size_t goff = ((size_t)(b * NTOK + row)) * QKVN + m * 256 + (h0 + lh) * HD + ch * 8;
        uint32_t d = sb + (uint32_t)(arr6 * 2) * AT_ARR + swz((uint32_t)row, (uint32_t)ch);
        CP_ASYNC16(d, qh_g + goff);
        CP_ASYNC16(d + AT_ARR, ql_g + goff);
    }
    CP_COMMIT();
    for (int u = tid; u < 336; u += 160) {      // 6 arr6 x 14 rows x 4 ch / ... = 6*56
        int arr6 = u / 56;
        int rem = u - arr6 * 56;
        int row = 66 + (rem >> 2), ch = rem & 3;
        uint32_t d = sb + (uint32_t)(arr6 * 2) * AT_ARR + swz((uint32_t)row, (uint32_t)ch);
        *(uint4*)(smc + (d - sb)) = make_uint4(0, 0, 0, 0);
        *(uint4*)(smc + (d - sb) + AT_ARR) = make_uint4(0, 0, 0, 0);
    }
    for (int t = tid; t < 1800; t += 160) tab[t] = table[t];
    asm volatile("cp.async.wait_group 0;" ::: "memory");
    __syncthreads();

    const int a_row = lane & 15;
    const int b_row = (lane & 7) + ((lane >> 4) << 3);
    const int i0 = wid * 16 + (lane >> 2);
    const int i1 = i0 + 8;

    for (int lh = 0; lh < 2; lh++) {
        const int hh = h0 + lh;
        const uint32_t QH = sb + (uint32_t)((lh * 3 + 0) * 2) * AT_ARR;
        const uint32_t KH = sb + (uint32_t)((lh * 3 + 1) * 2) * AT_ARR;
        const uint32_t VH = sb + (uint32_t)((lh * 3 + 2) * 2) * AT_ARR;

        // ---- S = Q K^T for this warp's 16-row stripe (cols 0..79) ----
        float sacc[10][4];
#pragma unroll
        for (int t = 0; t < 10; t++)
#pragma unroll
            for (int e = 0; e < 4; e++) sacc[t][e] = 0.f;
#pragma unroll
        for (int ks = 0; ks < 2; ks++) {
            uint32_t qh[4], ql[4];
            uint32_t aoff = swz((uint32_t)(wid * 16 + a_row),
                                (uint32_t)(ks * 2 + (lane >> 4)));
            ldsm4(qh, QH + aoff);
            ldsm4(ql, QH + AT_ARR + aoff);
#pragma unroll
            for (int ng = 0; ng < 5; ng++) {
                uint32_t kh[4], kl[4];
                uint32_t boff = swz((uint32_t)(ng * 16 + b_row),
                                    (uint32_t)(ks * 2 + ((lane >> 3) & 1)));
                ldsm4(kh, KH + boff);
                ldsm4(kl, KH + AT_ARR + boff);
#pragma unroll
                for (int nj = 0; nj < 2; nj++) {
                    float* c = sacc[ng * 2 + nj];
                    mma_bf16(c, qh, kh[nj * 2], kh[nj * 2 + 1]);
                    mma_bf16(c, qh, kl[nj * 2], kl[nj * 2 + 1]);
                    mma_bf16(c, ql, kh[nj * 2], kh[nj * 2 + 1]);
                }
            }
        }

        // ---- in-register softmax with scale + bias + pad mask ----
        float mx0 = -1e30f, mx1 = -1e30f;
#pragma unroll
        for (int t = 0; t < 10; t++)
#pragma unroll
            for (int e = 0; e < 4; e++) {
                int i = (e < 2) ? i0 : i1;
                int j = t * 8 + ((lane & 3) << 1) + (e & 1);
                float v = sacc[t][e] * scale;
                if (j >= NTOK) v = -1e30f;
                else if (i >= TOKNUM && i < NTOK && j >= TOKNUM) {
                    int yi = (i - TOKNUM) >> 3, xi = (i - TOKNUM) & 7;
                    int yj = (j - TOKNUM) >> 3, xj = (j - TOKNUM) & 7;
                    v += tab[((yi - yj + 7) * 15 + (xi - xj + 7)) * NHEAD + hh];
                }
                sacc[t][e] = v;
                if (e < 2) mx0 = fmaxf(mx0, v); else mx1 = fmaxf(mx1, v);
            }
        mx0 = fmaxf(mx0, __shfl_xor_sync(0xFFFFFFFFu, mx0, 1));
        mx0 = fmaxf(mx0, __shfl_xor_sync(0xFFFFFFFFu, mx0, 2));
        mx1 = fmaxf(mx1, __shfl_xor_sync(0xFFFFFFFFu, mx1, 1));
        mx1 = fmaxf(mx1, __shfl_xor_sync(0xFFFFFFFFu, mx1, 2));
        float l0 = 0.f, l1 = 0.f;
#pragma unroll
        for (int t = 0; t < 10; t++)
#pragma unroll
            for (int e = 0; e < 4; e++) {
                float p = __expf(sacc[t][e] - ((e < 2) ? mx0 : mx1));
                sacc[t][e] = p;
                if (e < 2) l0 += p; else l1 += p;
            }
        l0 += __shfl_xor_sync(0xFFFFFFFFu, l0, 1);
        l0 += __shfl_xor_sync(0xFFFFFFFFu, l0, 2);
        l1 += __shfl_xor_sync(0xFFFFFFFFu, l1, 1);
        l1 += __shfl_xor_sync(0xFFFFFFFFu, l1, 2);
        const float inv0 = 1.0f / l0;
        const float inv1 = 1.0f / l1;

        // ---- O = P V  (P re-packed C-frag -> A-frag in registers) ----
        float oacc[4][4];
#pragma unroll
        for (int nt = 0; nt < 4; nt++)
#pragma unroll
            for (int e = 0; e < 4; e++) oacc[nt][e] = 0.f;
#pragma unroll
        for (int g = 0; g < 5; g++) {
            uint32_t pah[4], pal[4];
            pah[0] = pack_bf2(sacc[2 * g][0], sacc[2 * g][1]);
            pah[1] = pack_bf2(sacc[2 * g][2], sacc[2 * g][3]);
            pah[2] = pack_bf2(sacc[2 * g + 1][0], sacc[2 * g + 1][1]);
            pah[3] = pack_bf2(sacc[2 * g + 1][2], sacc[2 * g + 1][3]);
            pal[0] = pack_bf2(bf_lo(sacc[2 * g][0]), bf_lo(sacc[2 * g][1]));
            pal[1] = pack_bf2(bf_lo(sacc[2 * g][2]), bf_lo(sacc[2 * g][3]));
            pal[2] = pack_bf2(bf_lo(sacc[2 * g + 1][0]), bf_lo(sacc[2 * g + 1][1]));
            pal[3] = pack_bf2(bf_lo(sacc[2 * g + 1][2]), bf_lo(sacc[2 * g + 1][3]));
#pragma unroll
            for (int ng = 0; ng < 2; ng++) {
                uint32_t vh[4], vl[4];
                uint32_t vrow = (uint32_t)(g * 16 + (lane & 7) + (((lane >> 3) & 1) << 3));
                uint32_t vch  = (uint32_t)(ng * 2 + (lane >> 4));
                uint32_t boff = swz(vrow, vch);
                ldsm4t(vh, VH + boff);
                ldsm4t(vl, VH + AT_ARR + boff);
#pragma unroll
                for (int nj = 0; nj < 2; nj++) {
                    float* c = oacc[ng * 2 + nj];
                    mma_bf16(c, pah, vh[nj * 2], vh[nj * 2 + 1]);
                    mma_bf16(c, pah, vl[nj * 2], vl[nj * 2 + 1]);
                    mma_bf16(c, pal, vh[nj * 2], vh[nj * 2 + 1]);
                }
            }
        }

        // ---- normalize + hi/lo store ----
#pragma unroll
        for (int nt = 0; nt < 4; nt++) {
            int col = hh * HD + nt * 8 + (lane & 3) * 2;
            if (i0 < NTOK) {
                float o0 = oacc[nt][0] * inv0, o1 = oacc[nt][1] * inv0;
                size_t off = ((size_t)b * NTOK + i0) * DIM + col;
                *(uint32_t*)&ohi[off] = pack_bf2(o0, o1);
                *(uint32_t*)&olo[off] = pack_bf2(bf_lo(o0), bf_lo(o1));
            }
            if (i1 < NTOK) {
                float o2 = oacc[nt][2] * inv1, o3 = oacc[nt][3] * inv1;
                size_t off = ((size_t)b * NTOK + i1) * DIM + col;
                *(uint32_t*)&ohi[off] = pack_bf2(o2, o3);
                *(uint32_t*)&olo[off] = pack_bf2(bf_lo(o2), bf_lo(o3));
            }
        }
    }
}

// ---------------------------------------------------------------------------
extern "C" void kernel_launch(void* const* d_in, const int* in_sizes, int n_in,
                              void* d_out, int out_size)
{
    const float* x      = (const float*)d_in[0];
    const float* qkv_w  = (const float*)d_in[1];
    const float* qkv_b  = (const float*)d_in[2];
    const float* table  = (const float*)d_in[3];
    const float* proj_w = (const float*)d_in[4];
    const float* proj_b = (const float*)d_in[5];
    float* out = (float*)d_out;

    __nv_bfloat16 *qkvhi, *qkvlo, *xhi, *xlo, *ahi, *alo, *qwhi, *qwlo, *pwhi, *pwlo;
    cudaGetSymbolAddress((void**)&qkvhi, g_qkvhi);
    cudaGetSymbolAddress((void**)&qkvlo, g_qkvlo);
    cudaGetSymbolAddress((void**)&xhi,  g_xhi);
    cudaGetSymbolAddress((void**)&xlo,  g_xlo);
    cudaGetSymbolAddress((void**)&ahi,  g_ahi);
    cudaGetSymbolAddress((void**)&alo,  g_alo);
    cudaGetSymbolAddress((void**)&qwhi, g_qwhi);
    cudaGetSymbolAddress((void**)&qwlo, g_qwlo);
    cudaGetSymbolAddress((void**)&pwhi, g_pwhi);
    cudaGetSymbolAddress((void**)&pwlo, g_pwlo);

    cudaFuncSetAttribute(gemm_mma_kernel,   cudaFuncAttributeMaxDynamicSharedMemorySize, GEMM_SMEM);
    cudaFuncSetAttribute(attn_flash_kernel, cudaFuncAttributeMaxDynamicSharedMemorySize, ATT_SMEM);

    {
        int n4 = MTOT * DIM / 4;
        split_kernel<<<(n4 + 255) / 256, 256>>>(x, xhi, xlo, n4);
        int w4 = QKVN * DIM / 4;
        split_kernel<<<(w4 + 255) / 256, 256>>>(qkv_w, qwhi, qwlo, w4);
        int p4 = DIM * DIM / 4;
        split_kernel<<<(p4 + 255) / 256, 256>>>(proj_w, pwhi, pwlo, p4);
    }

    // QKV projection -> bf16 hi/lo (no fp32 intermediate)
    gemm_mma_kernel<<<dim3(MTOT / BM, QKVN / BN), 256, GEMM_SMEM>>>(
        xhi, xlo, qwhi, qwlo, qkv_b, nullptr, qkvhi, qkvlo, QKVN);

    // flash MMA attention (reads hi/lo, writes hi/lo)
    attn_flash_kernel<<<dim3(NWIN, NHEAD / 2), 160, ATT_SMEM>>>(
        qkvhi, qkvlo, table, ahi, alo);

    // output projection -> fp32 d_out
    gemm_mma_kernel<<<dim3(MTOT / BM, DIM / BN), 256, GEMM_SMEM>>>(
        ahi, alo, pwhi, pwlo, proj_b, out, nullptr, nullptr, DIM);
}